// round 7
// baseline (speedup 1.0000x reference)
#include <cuda_runtime.h>
#include <cuda_bf16.h>
#include <cstdint>

#define HID   2048
#define HD    128
#define NH    16
#define BATCH 2
#define SEQ   2048
#define MROWS (BATCH*SEQ)   // 4096

// Scratch (no allocation allowed -> __device__ globals)
__device__ float g_q[(size_t)MROWS * HID];
__device__ float g_k[(size_t)MROWS * HD];
__device__ float g_v[(size_t)MROWS * HD];
__device__ float g_o[(size_t)MROWS * HID];
__device__ float g_x[(size_t)MROWS * HID];   // tf32-rounded x
__device__ float g_wq[(size_t)HID * HID];    // tf32-rounded w_q
__device__ float g_wo[(size_t)HID * HID];    // tf32-rounded w_out

__device__ __forceinline__ uint32_t cvt_tf32(float x) {
    uint32_t r; asm("cvt.rna.tf32.f32 %0, %1;" : "=r"(r) : "f"(x)); return r;
}

__device__ __forceinline__ void mma_tf32(float* d, const uint32_t* a,
                                         const uint32_t* b, const float* c) {
    asm volatile(
        "mma.sync.aligned.m16n8k8.row.col.f32.tf32.tf32.f32 "
        "{%0,%1,%2,%3}, {%4,%5,%6,%7}, {%8,%9}, {%10,%11,%12,%13};"
        : "=f"(d[0]), "=f"(d[1]), "=f"(d[2]), "=f"(d[3])
        : "r"(a[0]), "r"(a[1]), "r"(a[2]), "r"(a[3]),
          "r"(b[0]), "r"(b[1]),
          "f"(c[0]), "f"(c[1]), "f"(c[2]), "f"(c[3]));
}

__device__ __forceinline__ void cp16(uint32_t dst, const void* src) {
    asm volatile("cp.async.ca.shared.global [%0], [%1], 16;" :: "r"(dst), "l"(src));
}
#define CP_COMMIT() asm volatile("cp.async.commit_group;" ::: "memory")
#define CP_WAIT(n)  asm volatile("cp.async.wait_group %0;" :: "n"(n) : "memory")

__device__ __forceinline__ uint32_t smem_u32(const void* p) {
    uint32_t a;
    asm("{ .reg .u64 t; cvta.to.shared.u64 t, %1; cvt.u32.u64 %0, t; }"
        : "=r"(a) : "l"(p));
    return a;
}

// ===========================================================================
// Pre-pass: RNA-round three arrays to tf32 (so cp.async paths carry exact tf32)
// ===========================================================================
__global__ void round3_tf32(const float* __restrict__ a, float* __restrict__ ao, int na4,
                            const float* __restrict__ b, float* __restrict__ bo, int nb4,
                            const float* __restrict__ c, float* __restrict__ co, int nc4)
{
    int total = na4 + nb4 + nc4;
    for (int i = blockIdx.x * blockDim.x + threadIdx.x; i < total;
         i += gridDim.x * blockDim.x) {
        const float4* src; float4* dst; int j = i;
        if (j < na4) { src = (const float4*)a; dst = (float4*)ao; }
        else if ((j -= na4) < nb4) { src = (const float4*)b; dst = (float4*)bo; }
        else { j -= nb4; src = (const float4*)c; dst = (float4*)co; }
        float4 v = src[j];
        v.x = __uint_as_float(cvt_tf32(v.x));
        v.y = __uint_as_float(cvt_tf32(v.y));
        v.z = __uint_as_float(cvt_tf32(v.z));
        v.w = __uint_as_float(cvt_tf32(v.w));
        dst[j] = v;
    }
}

// ===========================================================================
// Wide tf32 GEMM: C[M,N] = A[M,K] * B[N,K]^T. CTA 128x256, 8 warps of 64x64.
// Inputs must already be tf32-valued. cp.async double-buffered, BK=32.
// ===========================================================================
#define WPAD  36
#define WASZ  (128 * WPAD)
#define WBSZ  (256 * WPAD)
#define WSTG  (WASZ + WBSZ)
#define WSMEM (2 * WSTG * 4)

__global__ __launch_bounds__(256, 1) void gemm_wide(
    const float* __restrict__ A, const float* __restrict__ B,
    float* __restrict__ C, int M, int N, int K, int round_out)
{
    extern __shared__ float smf[];
    const uint32_t sb = smem_u32(smf);
    const int tid  = threadIdx.x;
    const int wid  = tid >> 5;
    const int lane = tid & 31;
    const int grp  = lane >> 2;
    const int tg   = lane & 3;
    const int wm   = (wid & 1) * 64;
    const int wn   = (wid >> 1) * 64;
    const int m0 = blockIdx.y * 128;
    const int n0 = blockIdx.x * 256;

    float acc[4][8][4];
#pragma unroll
    for (int i = 0; i < 4; i++)
#pragma unroll
        for (int j = 0; j < 8; j++)
#pragma unroll
            for (int r = 0; r < 4; r++) acc[i][j][r] = 0.f;

    const int nch = K / 32;

    auto load_stage = [&](int c, int buf) {
        const int k0 = c * 32;
        const uint32_t base = sb + buf * WSTG * 4;
#pragma unroll
        for (int i = 0; i < 4; i++) {
            int g = tid + i * 256;
            int r = g >> 3, c4 = (g & 7) * 4;
            cp16(base + (r * WPAD + c4) * 4, &A[(size_t)(m0 + r) * K + k0 + c4]);
        }
#pragma unroll
        for (int i = 0; i < 8; i++) {
            int g = tid + i * 256;
            int r = g >> 3, c4 = (g & 7) * 4;
            cp16(base + (WASZ + r * WPAD + c4) * 4, &B[(size_t)(n0 + r) * K + k0 + c4]);
        }
        CP_COMMIT();
    };

    load_stage(0, 0);

    for (int c = 0; c < nch; c++) {
        CP_WAIT(0);
        __syncthreads();
        if (c + 1 < nch) load_stage(c + 1, (c + 1) & 1);

        const float* sA = smf + (c & 1) * WSTG;
        const float* sB = sA + WASZ;

#pragma unroll
        for (int ks = 0; ks < 4; ks++) {
            const int k0 = ks * 8;
            uint32_t afr[4][4], bfr[8][2];
#pragma unroll
            for (int mf = 0; mf < 4; mf++) {
                int row = wm + mf * 16 + grp;
                afr[mf][0] = __float_as_uint(sA[row * WPAD + k0 + tg]);
                afr[mf][1] = __float_as_uint(sA[(row + 8) * WPAD + k0 + tg]);
                afr[mf][2] = __float_as_uint(sA[row * WPAD + k0 + tg + 4]);
                afr[mf][3] = __float_as_uint(sA[(row + 8) * WPAD + k0 + tg + 4]);
            }
#pragma unroll
            for (int nf = 0; nf < 8; nf++) {
                int col = wn + nf * 8 + grp;
                bfr[nf][0] = __float_as_uint(sB[col * WPAD + k0 + tg]);
                bfr[nf][1] = __float_as_uint(sB[col * WPAD + k0 + tg + 4]);
            }
#pragma unroll
            for (int mf = 0; mf < 4; mf++)
#pragma unroll
                for (int nf = 0; nf < 8; nf++)
                    mma_tf32(acc[mf][nf], afr[mf], bfr[nf], acc[mf][nf]);
        }
    }

#pragma unroll
    for (int mf = 0; mf < 4; mf++) {
#pragma unroll
        for (int nf = 0; nf < 8; nf++) {
            int row = m0 + wm + mf * 16 + grp;
            int col = n0 + wn + nf * 8 + tg * 2;
            float v0 = acc[mf][nf][0], v1 = acc[mf][nf][1];
            float v2 = acc[mf][nf][2], v3 = acc[mf][nf][3];
            if (round_out) {
                v0 = __uint_as_float(cvt_tf32(v0));
                v1 = __uint_as_float(cvt_tf32(v1));
                v2 = __uint_as_float(cvt_tf32(v2));
                v3 = __uint_as_float(cvt_tf32(v3));
            }
            *(float2*)&C[(size_t)row * N + col] = make_float2(v0, v1);
            *(float2*)&C[(size_t)(row + 8) * N + col] = make_float2(v2, v3);
        }
    }
}

// ===========================================================================
// Small GEMM (K/V projections, N=128)
// ===========================================================================
#define BK   32
#define PAD  36

__global__ __launch_bounds__(256, 2) void gemm_tf32(
    const float* __restrict__ A, const float* __restrict__ B,
    float* __restrict__ C, int M, int N, int K, int round_out,
    const float* __restrict__ B2, float* __restrict__ C2)
{
    __shared__ uint32_t As[128 * PAD];
    __shared__ uint32_t Bs[128 * PAD];

    if (blockIdx.z == 1) { B = B2; C = C2; }

    const int tid  = threadIdx.x;
    const int wid  = tid >> 5;
    const int lane = tid & 31;
    const int grp  = lane >> 2;
    const int tg   = lane & 3;
    const int wm   = (wid & 1) * 64;
    const int wn   = (wid >> 1) * 32;
    const int m0 = blockIdx.y * 128;
    const int n0 = blockIdx.x * 128;

    const int ldr  = tid >> 3;
    const int ldc  = (tid & 7) * 4;

    float acc[4][4][4];
#pragma unroll
    for (int i = 0; i < 4; i++)
#pragma unroll
        for (int j = 0; j < 4; j++)
#pragma unroll
            for (int r = 0; r < 4; r++) acc[i][j][r] = 0.f;

    const int nchunks = K / BK;
    float4 pa[4], pb[4];

#pragma unroll
    for (int it = 0; it < 4; it++) {
        int r = ldr + it * 32;
        pa[it] = *(const float4*)&A[(size_t)(m0 + r) * K + ldc];
        pb[it] = *(const float4*)&B[(size_t)(n0 + r) * K + ldc];
    }

    for (int c = 0; c < nchunks; c++) {
#pragma unroll
        for (int it = 0; it < 4; it++) {
            int r = ldr + it * 32;
            As[r * PAD + ldc + 0] = cvt_tf32(pa[it].x);
            As[r * PAD + ldc + 1] = cvt_tf32(pa[it].y);
            As[r * PAD + ldc + 2] = cvt_tf32(pa[it].z);
            As[r * PAD + ldc + 3] = cvt_tf32(pa[it].w);
            Bs[r * PAD + ldc + 0] = cvt_tf32(pb[it].x);
            Bs[r * PAD + ldc + 1] = cvt_tf32(pb[it].y);
            Bs[r * PAD + ldc + 2] = cvt_tf32(pb[it].z);
            Bs[r * PAD + ldc + 3] = cvt_tf32(pb[it].w);
        }
        __syncthreads();

        if (c + 1 < nchunks) {
            const int k0 = (c + 1) * BK;
#pragma unroll
            for (int it = 0; it < 4; it++) {
                int r = ldr + it * 32;
                pa[it] = *(const float4*)&A[(size_t)(m0 + r) * K + k0 + ldc];
                pb[it] = *(const float4*)&B[(size_t)(n0 + r) * K + k0 + ldc];
            }
        }

#pragma unroll
        for (int ks = 0; ks < 4; ks++) {
            const int k0 = ks * 8;
            uint32_t afr[4][4], bfr[4][2];
#pragma unroll
            for (int mf = 0; mf < 4; mf++) {
                int row = wm + mf * 16 + grp;
                afr[mf][0] = As[row * PAD + k0 + tg];
                afr[mf][1] = As[(row + 8) * PAD + k0 + tg];
                afr[mf][2] = As[row * PAD + k0 + tg + 4];
                afr[mf][3] = As[(row + 8) * PAD + k0 + tg + 4];
            }
#pragma unroll
            for (int nf = 0; nf < 4; nf++) {
                int col = wn + nf * 8 + grp;
                bfr[nf][0] = Bs[col * PAD + k0 + tg];
                bfr[nf][1] = Bs[col * PAD + k0 + tg + 4];
            }
#pragma unroll
            for (int mf = 0; mf < 4; mf++)
#pragma unroll
                for (int nf = 0; nf < 4; nf++)
                    mma_tf32(acc[mf][nf], afr[mf], bfr[nf], acc[mf][nf]);
        }
        __syncthreads();
    }

#pragma unroll
    for (int mf = 0; mf < 4; mf++) {
#pragma unroll
        for (int nf = 0; nf < 4; nf++) {
            int row = m0 + wm + mf * 16 + grp;
            int col = n0 + wn + nf * 8 + tg * 2;
            float v0 = acc[mf][nf][0], v1 = acc[mf][nf][1];
            float v2 = acc[mf][nf][2], v3 = acc[mf][nf][3];
            if (round_out) {
                v0 = __uint_as_float(cvt_tf32(v0));
                v1 = __uint_as_float(cvt_tf32(v1));
                v2 = __uint_as_float(cvt_tf32(v2));
                v3 = __uint_as_float(cvt_tf32(v3));
            }
            *(float2*)&C[(size_t)row * N + col] = make_float2(v0, v1);
            *(float2*)&C[(size_t)(row + 8) * N + col] = make_float2(v2, v3);
        }
    }
}

// ===========================================================================
// Tensor-core flash MQA, spill-free: Q lives in SMEM (cp.async once per CTA,
// A-fragments reloaded per k-step); P rounded in place into s (no pf array).
// K double-buffered, V single-buffered. SMEM ~166 KB, 1 CTA/SM.
// ===========================================================================
#define BQ    128
#define BKEY  64
#define PADQ  132
#define PADK  132
#define PADV  136
#define OFF_Q  0
#define OFF_K0 16896
#define OFF_K1 25344
#define OFF_V  33792
#define FLASH_SMEM (42496 * 4)

__global__ __launch_bounds__(256, 1) void flash_mqa_tc(
    const float* __restrict__ Q, const float* __restrict__ Kg,
    const float* __restrict__ Vg, float* __restrict__ O)
{
    extern __shared__ float sm[];
    const uint32_t sb = smem_u32(sm);
    const int tid = threadIdx.x;
    const int wid = tid >> 5;
    const int lane = tid & 31;
    const int grp = lane >> 2;
    const int tg  = lane & 3;
    const int h = blockIdx.x & 15;
    const int b = blockIdx.x >> 4;
    const int q0 = blockIdx.y * BQ;
    const float scale = 0.08838834764831845f;   // 1/sqrt(128)

    const float* kb = Kg + (size_t)b * SEQ * HD;
    const float* vb = Vg + (size_t)b * SEQ * HD;
    const int nb = SEQ / BKEY;   // 32

    auto load_k = [&](int blk, uint32_t koff) {
        const float* src = kb + (size_t)blk * BKEY * HD;
#pragma unroll
        for (int it = 0; it < 8; it++) {
            int idx = tid + it * 256;
            int r = idx >> 5, ch = (idx & 31) * 4;
            cp16(sb + (koff + r * PADK + ch) * 4, src + (size_t)r * HD + ch);
        }
    };
    auto load_v = [&](int blk) {
        const float* src = vb + (size_t)blk * BKEY * HD;
#pragma unroll
        for (int it = 0; it < 8; it++) {
            int idx = tid + it * 256;
            int r = idx >> 5, ch = (idx & 31) * 4;
            cp16(sb + (OFF_V + r * PADV + ch) * 4, src + (size_t)r * HD + ch);
        }
    };

    // Q tile -> SMEM (tf32-valued in gmem; raw cp.async)
    {
        const float* qsrc = Q + (size_t)(b * SEQ + q0) * HID + h * HD;
#pragma unroll
        for (int it = 0; it < 16; it++) {
            int idx = tid + it * 256;          // 0..4095 granules
            int r = idx >> 5, ch = (idx & 31) * 4;
            cp16(sb + (OFF_Q + r * PADQ + ch) * 4, qsrc + (size_t)r * HID + ch);
        }
    }
    // Prologue groups: A={Q,K0,V0}, B={K1}
    load_k(0, OFF_K0); load_v(0); CP_COMMIT();
    load_k(1, OFF_K1); CP_COMMIT();

    float o[16][4];
#pragma unroll
    for (int i = 0; i < 16; i++)
#pragma unroll
        for (int j = 0; j < 4; j++) o[i][j] = 0.f;
    float m0r = -1e30f, m1r = -1e30f, l0 = 0.f, l1 = 0.f;

    const float* Qs = sm + OFF_Q + (size_t)(wid * 16) * PADQ;
    const int qsl  = (lane & ~3) | (tg >> 1);   // quad shuffle source lanes
    const int qsl2 = qsl + 2;

    for (int blk = 0; blk < nb; blk++) {
        CP_WAIT(1);
        __syncthreads();

        const float* Kp = sm + ((blk & 1) ? OFF_K1 : OFF_K0);
        const float* Vp = sm + OFF_V;

        // ---- S = Q * K^T ----
        float s[8][4];
#pragma unroll
        for (int nt = 0; nt < 8; nt++)
#pragma unroll
            for (int j = 0; j < 4; j++) s[nt][j] = 0.f;

#pragma unroll
        for (int ks = 0; ks < 16; ks++) {
            uint32_t af[4];
            af[0] = __float_as_uint(Qs[(size_t)grp * PADQ + ks * 8 + tg]);
            af[1] = __float_as_uint(Qs[(size_t)(grp + 8) * PADQ + ks * 8 + tg]);
            af[2] = __float_as_uint(Qs[(size_t)grp * PADQ + ks * 8 + tg + 4]);
            af[3] = __float_as_uint(Qs[(size_t)(grp + 8) * PADQ + ks * 8 + tg + 4]);
            uint32_t bf[8][2];
#pragma unroll
            for (int nt = 0; nt < 8; nt++) {
                bf[nt][0] = __float_as_uint(Kp[(nt * 8 + grp) * PADK + ks * 8 + tg]);
                bf[nt][1] = __float_as_uint(Kp[(nt * 8 + grp) * PADK + ks * 8 + tg + 4]);
            }
#pragma unroll
            for (int nt = 0; nt < 8; nt++)
                mma_tf32(s[nt], af, bf[nt], s[nt]);
        }

        // ---- online softmax; P tf32-rounded IN PLACE into s ----
        float ml0 = -1e30f, ml1 = -1e30f;
#pragma unroll
        for (int nt = 0; nt < 8; nt++) {
            ml0 = fmaxf(ml0, fmaxf(s[nt][0], s[nt][1]));
            ml1 = fmaxf(ml1, fmaxf(s[nt][2], s[nt][3]));
        }
        ml0 *= scale; ml1 *= scale;
#pragma unroll
        for (int off = 1; off < 4; off <<= 1) {
            ml0 = fmaxf(ml0, __shfl_xor_sync(0xffffffffu, ml0, off));
            ml1 = fmaxf(ml1, __shfl_xor_sync(0xffffffffu, ml1, off));
        }
        const float mn0 = fmaxf(m0r, ml0);
        const float mn1 = fmaxf(m1r, ml1);
        const float a0 = __expf(m0r - mn0);
        const float a1 = __expf(m1r - mn1);
        float sum0 = 0.f, sum1 = 0.f;
#pragma unroll
        for (int nt = 0; nt < 8; nt++) {
            float p00 = __expf(s[nt][0] * scale - mn0);
            float p01 = __expf(s[nt][1] * scale - mn0);
            float p10 = __expf(s[nt][2] * scale - mn1);
            float p11 = __expf(s[nt][3] * scale - mn1);
            sum0 += p00 + p01;
            sum1 += p10 + p11;
            s[nt][0] = __uint_as_float(cvt_tf32(p00));
            s[nt][1] = __uint_as_float(cvt_tf32(p01));
            s[nt][2] = __uint_as_float(cvt_tf32(p10));
            s[nt][3] = __uint_as_float(cvt_tf32(p11));
        }
#pragma unroll
        for (int off = 1; off < 4; off <<= 1) {
            sum0 += __shfl_xor_sync(0xffffffffu, sum0, off);
            sum1 += __shfl_xor_sync(0xffffffffu, sum1, off);
        }
        l0 = l0 * a0 + sum0;
        l1 = l1 * a1 + sum1;
        m0r = mn0; m1r = mn1;
#pragma unroll
        for (int nt = 0; nt < 16; nt++) {
            o[nt][0] *= a0; o[nt][1] *= a0;
            o[nt][2] *= a1; o[nt][3] *= a1;
        }

        // ---- O += P * V : A-fragments from s via quad shuffles ----
#pragma unroll
        for (int ks2 = 0; ks2 < 8; ks2++) {
            float e0, e1;
            uint32_t af[4];
            e0 = __shfl_sync(0xffffffffu, s[ks2][0], qsl);
            e1 = __shfl_sync(0xffffffffu, s[ks2][1], qsl);
            af[0] = __float_as_uint((tg & 1) ? e1 : e0);
            e0 = __shfl_sync(0xffffffffu, s[ks2][2], qsl);
            e1 = __shfl_sync(0xffffffffu, s[ks2][3], qsl);
            af[1] = __float_as_uint((tg & 1) ? e1 : e0);
            e0 = __shfl_sync(0xffffffffu, s[ks2][0], qsl2);
            e1 = __shfl_sync(0xffffffffu, s[ks2][1], qsl2);
            af[2] = __float_as_uint((tg & 1) ? e1 : e0);
            e0 = __shfl_sync(0xffffffffu, s[ks2][2], qsl2);
            e1 = __shfl_sync(0xffffffffu, s[ks2][3], qsl2);
            af[3] = __float_as_uint((tg & 1) ? e1 : e0);
#pragma unroll
            for (int nt = 0; nt < 16; nt++) {
                uint32_t bf2[2];
                bf2[0] = __float_as_uint(Vp[(ks2 * 8 + tg) * PADV + nt * 8 + grp]);
                bf2[1] = __float_as_uint(Vp[(ks2 * 8 + tg + 4) * PADV + nt * 8 + grp]);
                mma_tf32(o[nt], af, bf2, o[nt]);
            }
        }
        __syncthreads();   // all warps done with V(blk), K(blk)

        if (blk + 1 < nb) load_v(blk + 1);
        CP_COMMIT();
        if (blk + 2 < nb) load_k(blk + 2, (blk & 1) ? OFF_K1 : OFF_K0);
        CP_COMMIT();
    }

    // ---- epilogue (tf32-rounded for out-projection cp.async path) ----
    const float inv0 = 1.f / l0;
    const float inv1 = 1.f / l1;
    float* ob = O + (size_t)(b * SEQ + q0 + wid * 16) * HID + h * HD;
#pragma unroll
    for (int nt = 0; nt < 16; nt++) {
        int c = nt * 8 + 2 * tg;
        float v0 = __uint_as_float(cvt_tf32(o[nt][0] * inv0));
        float v1 = __uint_as_float(cvt_tf32(o[nt][1] * inv0));
        float v2 = __uint_as_float(cvt_tf32(o[nt][2] * inv1));
        float v3 = __uint_as_float(cvt_tf32(o[nt][3] * inv1));
        *(float2*)&ob[(size_t)grp * HID + c] = make_float2(v0, v1);
        *(float2*)&ob[(size_t)(grp + 8) * HID + c] = make_float2(v2, v3);
    }
}

// ===========================================================================
extern "C" void kernel_launch(void* const* d_in, const int* in_sizes, int n_in,
                              void* d_out, int out_size)
{
    const float* x  = (const float*)d_in[0];
    const float* wq = (const float*)d_in[1];
    const float* wk = (const float*)d_in[2];
    const float* wv = (const float*)d_in[3];
    const float* wo = (const float*)d_in[4];
    float* out = (float*)d_out;

    float *q, *k, *v, *o, *xr, *wqr, *wor;
    cudaGetSymbolAddress((void**)&q, g_q);
    cudaGetSymbolAddress((void**)&k, g_k);
    cudaGetSymbolAddress((void**)&v, g_v);
    cudaGetSymbolAddress((void**)&o, g_o);
    cudaGetSymbolAddress((void**)&xr, g_x);
    cudaGetSymbolAddress((void**)&wqr, g_wq);
    cudaGetSymbolAddress((void**)&wor, g_wo);

    cudaFuncSetAttribute(flash_mqa_tc,
                         cudaFuncAttributeMaxDynamicSharedMemorySize, FLASH_SMEM);
    cudaFuncSetAttribute(gemm_wide,
                         cudaFuncAttributeMaxDynamicSharedMemorySize, WSMEM);

    dim3 blk(256);

    // Round x, w_q, w_out to tf32
    round3_tf32<<<2048, 256>>>(x, xr, MROWS * HID / 4,
                               wq, wqr, HID * HID / 4,
                               wo, wor, HID * HID / 4);

    // Q projection (wide tensor GEMM, tf32-rounded output)
    gemm_wide<<<dim3(HID / 256, MROWS / 128), blk, WSMEM>>>(
        xr, wqr, q, MROWS, HID, HID, 1);

    // K and V projections fused (small GEMM)
    gemm_tf32<<<dim3(HD / 128, MROWS / 128, 2), blk>>>(
        x, wk, k, MROWS, HD, HID, 1, wv, v);

    // Tensor-core flash attention
    flash_mqa_tc<<<dim3(BATCH * NH, SEQ / BQ), blk, FLASH_SMEM>>>(q, k, v, o);

    // Output projection (wide tensor GEMM, full fp32 output)
    gemm_wide<<<dim3(HID / 256, MROWS / 128), blk, WSMEM>>>(
        o, wor, out, MROWS, HID, HID, 0);
}

// round 8
// speedup vs baseline: 1.6755x; 1.6755x over previous
#include <cuda_runtime.h>
#include <cuda_bf16.h>
#include <cstdint>

#define HID   2048
#define HD    128
#define NH    16
#define BATCH 2
#define SEQ   2048
#define MROWS (BATCH*SEQ)   // 4096

// Scratch (no allocation allowed -> __device__ globals)
__device__ float g_q[(size_t)MROWS * HID];
__device__ float g_k[(size_t)MROWS * HD];
__device__ float g_vt[(size_t)BATCH * HD * SEQ];   // V transposed: [b][d][s]
__device__ float g_o[(size_t)MROWS * HID];
__device__ float g_x[(size_t)MROWS * HID];   // tf32-rounded x
__device__ float g_wq[(size_t)HID * HID];    // tf32-rounded w_q
__device__ float g_wo[(size_t)HID * HID];    // tf32-rounded w_out

__device__ __forceinline__ uint32_t cvt_tf32(float x) {
    uint32_t r; asm("cvt.rna.tf32.f32 %0, %1;" : "=r"(r) : "f"(x)); return r;
}

__device__ __forceinline__ void mma_tf32(float* d, const uint32_t* a,
                                         const uint32_t* b, const float* c) {
    asm volatile(
        "mma.sync.aligned.m16n8k8.row.col.f32.tf32.tf32.f32 "
        "{%0,%1,%2,%3}, {%4,%5,%6,%7}, {%8,%9}, {%10,%11,%12,%13};"
        : "=f"(d[0]), "=f"(d[1]), "=f"(d[2]), "=f"(d[3])
        : "r"(a[0]), "r"(a[1]), "r"(a[2]), "r"(a[3]),
          "r"(b[0]), "r"(b[1]),
          "f"(c[0]), "f"(c[1]), "f"(c[2]), "f"(c[3]));
}

// ldmatrix x4: four 8x8-b16 tiles (= four 8x4 tiles of 32-bit words)
__device__ __forceinline__ void ldsm4(uint32_t& r0, uint32_t& r1,
                                      uint32_t& r2, uint32_t& r3, uint32_t addr) {
    asm volatile("ldmatrix.sync.aligned.m8n8.x4.shared.b16 {%0,%1,%2,%3}, [%4];"
                 : "=r"(r0), "=r"(r1), "=r"(r2), "=r"(r3) : "r"(addr));
}

__device__ __forceinline__ void cp16(uint32_t dst, const void* src) {
    asm volatile("cp.async.ca.shared.global [%0], [%1], 16;" :: "r"(dst), "l"(src));
}
#define CP_COMMIT() asm volatile("cp.async.commit_group;" ::: "memory")
#define CP_WAIT(n)  asm volatile("cp.async.wait_group %0;" :: "n"(n) : "memory")

__device__ __forceinline__ uint32_t smem_u32(const void* p) {
    uint32_t a;
    asm("{ .reg .u64 t; cvta.to.shared.u64 t, %1; cvt.u32.u64 %0, t; }"
        : "=r"(a) : "l"(p));
    return a;
}

// ===========================================================================
// Pre-pass: RNA-round three arrays to tf32
// ===========================================================================
__global__ void round3_tf32(const float* __restrict__ a, float* __restrict__ ao, int na4,
                            const float* __restrict__ b, float* __restrict__ bo, int nb4,
                            const float* __restrict__ c, float* __restrict__ co, int nc4)
{
    int total = na4 + nb4 + nc4;
    for (int i = blockIdx.x * blockDim.x + threadIdx.x; i < total;
         i += gridDim.x * blockDim.x) {
        const float4* src; float4* dst; int j = i;
        if (j < na4) { src = (const float4*)a; dst = (float4*)ao; }
        else if ((j -= na4) < nb4) { src = (const float4*)b; dst = (float4*)bo; }
        else { j -= nb4; src = (const float4*)c; dst = (float4*)co; }
        float4 v = src[j];
        v.x = __uint_as_float(cvt_tf32(v.x));
        v.y = __uint_as_float(cvt_tf32(v.y));
        v.z = __uint_as_float(cvt_tf32(v.z));
        v.w = __uint_as_float(cvt_tf32(v.w));
        dst[j] = v;
    }
}

// ===========================================================================
// Wide tf32 GEMM (unchanged from R6): C[M,N] = A[M,K]*B[N,K]^T, 128x256 CTA.
// ===========================================================================
#define WPAD  36
#define WASZ  (128 * WPAD)
#define WBSZ  (256 * WPAD)
#define WSTG  (WASZ + WBSZ)
#define WSMEM (2 * WSTG * 4)

__global__ __launch_bounds__(256, 1) void gemm_wide(
    const float* __restrict__ A, const float* __restrict__ B,
    float* __restrict__ C, int M, int N, int K, int round_out)
{
    extern __shared__ float smf[];
    const uint32_t sb = smem_u32(smf);
    const int tid  = threadIdx.x;
    const int wid  = tid >> 5;
    const int lane = tid & 31;
    const int grp  = lane >> 2;
    const int tg   = lane & 3;
    const int wm   = (wid & 1) * 64;
    const int wn   = (wid >> 1) * 64;
    const int m0 = blockIdx.y * 128;
    const int n0 = blockIdx.x * 256;

    float acc[4][8][4];
#pragma unroll
    for (int i = 0; i < 4; i++)
#pragma unroll
        for (int j = 0; j < 8; j++)
#pragma unroll
            for (int r = 0; r < 4; r++) acc[i][j][r] = 0.f;

    const int nch = K / 32;

    auto load_stage = [&](int c, int buf) {
        const int k0 = c * 32;
        const uint32_t base = sb + buf * WSTG * 4;
#pragma unroll
        for (int i = 0; i < 4; i++) {
            int g = tid + i * 256;
            int r = g >> 3, c4 = (g & 7) * 4;
            cp16(base + (r * WPAD + c4) * 4, &A[(size_t)(m0 + r) * K + k0 + c4]);
        }
#pragma unroll
        for (int i = 0; i < 8; i++) {
            int g = tid + i * 256;
            int r = g >> 3, c4 = (g & 7) * 4;
            cp16(base + (WASZ + r * WPAD + c4) * 4, &B[(size_t)(n0 + r) * K + k0 + c4]);
        }
        CP_COMMIT();
    };

    load_stage(0, 0);

    for (int c = 0; c < nch; c++) {
        CP_WAIT(0);
        __syncthreads();
        if (c + 1 < nch) load_stage(c + 1, (c + 1) & 1);

        const float* sA = smf + (c & 1) * WSTG;
        const float* sB = sA + WASZ;

#pragma unroll
        for (int ks = 0; ks < 4; ks++) {
            const int k0 = ks * 8;
            uint32_t afr[4][4], bfr[8][2];
#pragma unroll
            for (int mf = 0; mf < 4; mf++) {
                int row = wm + mf * 16 + grp;
                afr[mf][0] = __float_as_uint(sA[row * WPAD + k0 + tg]);
                afr[mf][1] = __float_as_uint(sA[(row + 8) * WPAD + k0 + tg]);
                afr[mf][2] = __float_as_uint(sA[row * WPAD + k0 + tg + 4]);
                afr[mf][3] = __float_as_uint(sA[(row + 8) * WPAD + k0 + tg + 4]);
            }
#pragma unroll
            for (int nf = 0; nf < 8; nf++) {
                int col = wn + nf * 8 + grp;
                bfr[nf][0] = __float_as_uint(sB[col * WPAD + k0 + tg]);
                bfr[nf][1] = __float_as_uint(sB[col * WPAD + k0 + tg + 4]);
            }
#pragma unroll
            for (int mf = 0; mf < 4; mf++)
#pragma unroll
                for (int nf = 0; nf < 8; nf++)
                    mma_tf32(acc[mf][nf], afr[mf], bfr[nf], acc[mf][nf]);
        }
    }

#pragma unroll
    for (int mf = 0; mf < 4; mf++) {
#pragma unroll
        for (int nf = 0; nf < 8; nf++) {
            int row = m0 + wm + mf * 16 + grp;
            int col = n0 + wn + nf * 8 + tg * 2;
            float v0 = acc[mf][nf][0], v1 = acc[mf][nf][1];
            float v2 = acc[mf][nf][2], v3 = acc[mf][nf][3];
            if (round_out) {
                v0 = __uint_as_float(cvt_tf32(v0));
                v1 = __uint_as_float(cvt_tf32(v1));
                v2 = __uint_as_float(cvt_tf32(v2));
                v3 = __uint_as_float(cvt_tf32(v3));
            }
            *(float2*)&C[(size_t)row * N + col] = make_float2(v0, v1);
            *(float2*)&C[(size_t)(row + 8) * N + col] = make_float2(v2, v3);
        }
    }
}

// ===========================================================================
// Small GEMM: K proj (z==0) writes C normally; V proj (z==1) writes Vt
// TRANSPOSED [b][d][s]. Both tf32-rounded.
// ===========================================================================
#define BK   32
#define PAD  36

__global__ __launch_bounds__(256, 2) void gemm_kv(
    const float* __restrict__ A, const float* __restrict__ Bk,
    float* __restrict__ C, int M, int N, int K,
    const float* __restrict__ Bv, float* __restrict__ Vt)
{
    __shared__ uint32_t As[128 * PAD];
    __shared__ uint32_t Bs[128 * PAD];

    const float* B = (blockIdx.z == 1) ? Bv : Bk;

    const int tid  = threadIdx.x;
    const int wid  = tid >> 5;
    const int lane = tid & 31;
    const int grp  = lane >> 2;
    const int tg   = lane & 3;
    const int wm   = (wid & 1) * 64;
    const int wn   = (wid >> 1) * 32;
    const int m0 = blockIdx.y * 128;
    const int n0 = blockIdx.x * 128;

    const int ldr  = tid >> 3;
    const int ldc  = (tid & 7) * 4;

    float acc[4][4][4];
#pragma unroll
    for (int i = 0; i < 4; i++)
#pragma unroll
        for (int j = 0; j < 4; j++)
#pragma unroll
            for (int r = 0; r < 4; r++) acc[i][j][r] = 0.f;

    const int nchunks = K / BK;
    float4 pa[4], pb[4];

#pragma unroll
    for (int it = 0; it < 4; it++) {
        int r = ldr + it * 32;
        pa[it] = *(const float4*)&A[(size_t)(m0 + r) * K + ldc];
        pb[it] = *(const float4*)&B[(size_t)(n0 + r) * K + ldc];
    }

    for (int c = 0; c < nchunks; c++) {
#pragma unroll
        for (int it = 0; it < 4; it++) {
            int r = ldr + it * 32;
            As[r * PAD + ldc + 0] = cvt_tf32(pa[it].x);
            As[r * PAD + ldc + 1] = cvt_tf32(pa[it].y);
            As[r * PAD + ldc + 2] = cvt_tf32(pa[it].z);
            As[r * PAD + ldc + 3] = cvt_tf32(pa[it].w);
            Bs[r * PAD + ldc + 0] = cvt_tf32(pb[it].x);
            Bs[r * PAD + ldc + 1] = cvt_tf32(pb[it].y);
            Bs[r * PAD + ldc + 2] = cvt_tf32(pb[it].z);
            Bs[r * PAD + ldc + 3] = cvt_tf32(pb[it].w);
        }
        __syncthreads();

        if (c + 1 < nchunks) {
            const int k0 = (c + 1) * BK;
#pragma unroll
            for (int it = 0; it < 4; it++) {
                int r = ldr + it * 32;
                pa[it] = *(const float4*)&A[(size_t)(m0 + r) * K + k0 + ldc];
                pb[it] = *(const float4*)&B[(size_t)(n0 + r) * K + k0 + ldc];
            }
        }

#pragma unroll
        for (int ks = 0; ks < 4; ks++) {
            const int k0 = ks * 8;
            uint32_t afr[4][4], bfr[4][2];
#pragma unroll
            for (int mf = 0; mf < 4; mf++) {
                int row = wm + mf * 16 + grp;
                afr[mf][0] = As[row * PAD + k0 + tg];
                afr[mf][1] = As[(row + 8) * PAD + k0 + tg];
                afr[mf][2] = As[row * PAD + k0 + tg + 4];
                afr[mf][3] = As[(row + 8) * PAD + k0 + tg + 4];
            }
#pragma unroll
            for (int nf = 0; nf < 4; nf++) {
                int col = wn + nf * 8 + grp;
                bfr[nf][0] = Bs[col * PAD + k0 + tg];
                bfr[nf][1] = Bs[col * PAD + k0 + tg + 4];
            }
#pragma unroll
            for (int mf = 0; mf < 4; mf++)
#pragma unroll
                for (int nf = 0; nf < 4; nf++)
                    mma_tf32(acc[mf][nf], afr[mf], bfr[nf], acc[mf][nf]);
        }
        __syncthreads();
    }

#pragma unroll
    for (int mf = 0; mf < 4; mf++) {
#pragma unroll
        for (int nf = 0; nf < 4; nf++) {
            int row = m0 + wm + mf * 16 + grp;
            int col = n0 + wn + nf * 8 + tg * 2;
            float v0 = __uint_as_float(cvt_tf32(acc[mf][nf][0]));
            float v1 = __uint_as_float(cvt_tf32(acc[mf][nf][1]));
            float v2 = __uint_as_float(cvt_tf32(acc[mf][nf][2]));
            float v3 = __uint_as_float(cvt_tf32(acc[mf][nf][3]));
            if (blockIdx.z == 0) {
                *(float2*)&C[(size_t)row * N + col] = make_float2(v0, v1);
                *(float2*)&C[(size_t)(row + 8) * N + col] = make_float2(v2, v3);
            } else {
                // transposed store: Vt[b][d][s], row = b*SEQ+s (128 | 2048)
                int b = row >> 11, s = row & 2047;
                Vt[((size_t)b * HD + col) * SEQ + s]           = v0;
                Vt[((size_t)b * HD + col + 1) * SEQ + s]       = v1;
                Vt[((size_t)b * HD + col) * SEQ + s + 8]       = v2;
                Vt[((size_t)b * HD + col + 1) * SEQ + s + 8]   = v3;
            }
        }
    }
}

// ===========================================================================
// Tensor-core flash MQA (R6 structure: Q frags in regs, P in regs) with
// ldmatrix.x4 for both K and V^T fragments.
// ===========================================================================
#define BQ    128
#define BKEY  64
#define PADK  132
#define PADVT 68
#define OFF_K0 0
#define OFF_K1 (64 * PADK)            // 8448
#define OFF_VT (2 * 64 * PADK)        // 16896
#define FLASH_SMEM ((OFF_VT + 128 * PADVT) * 4)   // 102400 B

__global__ __launch_bounds__(256, 1) void flash_mqa_tc(
    const float* __restrict__ Q, const float* __restrict__ Kg,
    const float* __restrict__ VTg, float* __restrict__ O)
{
    extern __shared__ float sm[];
    const uint32_t sb = smem_u32(sm);
    const int tid = threadIdx.x;
    const int wid = tid >> 5;
    const int lane = tid & 31;
    const int grp = lane >> 2;
    const int tg  = lane & 3;
    const int h = blockIdx.x & 15;
    const int b = blockIdx.x >> 4;
    const int q0 = blockIdx.y * BQ;
    const float scale = 0.08838834764831845f;   // 1/sqrt(128)

    const float* kb  = Kg + (size_t)b * SEQ * HD;
    const float* vtb = VTg + (size_t)b * HD * SEQ;
    const int nb = SEQ / BKEY;   // 32

    auto load_k = [&](int blk, uint32_t koff) {
        const float* src = kb + (size_t)blk * BKEY * HD;
#pragma unroll
        for (int it = 0; it < 8; it++) {
            int idx = tid + it * 256;
            int r = idx >> 5, ch = (idx & 31) * 4;
            cp16(sb + (koff + r * PADK + ch) * 4, src + (size_t)r * HD + ch);
        }
    };
    auto load_vt = [&](int blk) {
        const float* src = vtb + blk * BKEY;   // cols blk*64..+63 of [128][SEQ]
#pragma unroll
        for (int it = 0; it < 8; it++) {
            int idx = tid + it * 256;          // 0..2047 granules
            int r = idx >> 4, ch = (idx & 15) * 4;   // 128 rows x 16 granules
            cp16(sb + (OFF_VT + r * PADVT + ch) * 4, src + (size_t)r * SEQ + ch);
        }
    };

    // Q fragments in registers (tf32-valued in gmem)
    uint32_t qf[16][4];
    {
        const float* qbase = Q + (size_t)(b * SEQ + q0 + wid * 16) * HID + h * HD;
#pragma unroll
        for (int ks = 0; ks < 16; ks++) {
            qf[ks][0] = __float_as_uint(qbase[(size_t)grp * HID + ks * 8 + tg]);
            qf[ks][1] = __float_as_uint(qbase[(size_t)(grp + 8) * HID + ks * 8 + tg]);
            qf[ks][2] = __float_as_uint(qbase[(size_t)grp * HID + ks * 8 + tg + 4]);
            qf[ks][3] = __float_as_uint(qbase[(size_t)(grp + 8) * HID + ks * 8 + tg + 4]);
        }
    }

    float o[16][4];
#pragma unroll
    for (int i = 0; i < 16; i++)
#pragma unroll
        for (int j = 0; j < 4; j++) o[i][j] = 0.f;
    float m0r = -1e30f, m1r = -1e30f, l0 = 0.f, l1 = 0.f;

    load_k(0, OFF_K0); load_vt(0); CP_COMMIT();
    load_k(1, OFF_K1); CP_COMMIT();

    // ldmatrix lane geometry: tile = lane>>3, row-in-tile = lane&7
    const int lrow8 = ((lane >> 4) & 1) * 8 + (lane & 7);  // nt-within-pair*8+row
    const int lcolh = ((lane >> 3) & 1) * 4;               // k-half (floats)
    const int qsl  = (lane & ~3) | (tg >> 1);
    const int qsl2 = qsl + 2;

    for (int blk = 0; blk < nb; blk++) {
        CP_WAIT(1);
        __syncthreads();

        const uint32_t kOff = sb + ((blk & 1) ? OFF_K1 : OFF_K0) * 4;
        const uint32_t vOff = sb + OFF_VT * 4;

        // ---- S = Q * K^T : K fragments via ldmatrix.x4 (2 nt per LDSM) ----
        float s[8][4];
#pragma unroll
        for (int nt = 0; nt < 8; nt++)
#pragma unroll
            for (int j = 0; j < 4; j++) s[nt][j] = 0.f;

#pragma unroll
        for (int ks = 0; ks < 16; ks++) {
#pragma unroll
            for (int p = 0; p < 4; p++) {
                uint32_t b0, b1, b2, b3;
                uint32_t addr = kOff +
                    (uint32_t)(((p * 16 + lrow8) * PADK + ks * 8 + lcolh) * 4);
                ldsm4(b0, b1, b2, b3, addr);
                uint32_t bf0[2] = {b0, b1}, bf1[2] = {b2, b3};
                mma_tf32(s[2 * p],     qf[ks], bf0, s[2 * p]);
                mma_tf32(s[2 * p + 1], qf[ks], bf1, s[2 * p + 1]);
            }
        }

        // ---- online softmax; P tf32-rounded in place ----
        float ml0 = -1e30f, ml1 = -1e30f;
#pragma unroll
        for (int nt = 0; nt < 8; nt++) {
            ml0 = fmaxf(ml0, fmaxf(s[nt][0], s[nt][1]));
            ml1 = fmaxf(ml1, fmaxf(s[nt][2], s[nt][3]));
        }
        ml0 *= scale; ml1 *= scale;
#pragma unroll
        for (int off = 1; off < 4; off <<= 1) {
            ml0 = fmaxf(ml0, __shfl_xor_sync(0xffffffffu, ml0, off));
            ml1 = fmaxf(ml1, __shfl_xor_sync(0xffffffffu, ml1, off));
        }
        const float mn0 = fmaxf(m0r, ml0);
        const float mn1 = fmaxf(m1r, ml1);
        const float a0 = __expf(m0r - mn0);
        const float a1 = __expf(m1r - mn1);
        float sum0 = 0.f, sum1 = 0.f;
#pragma unroll
        for (int nt = 0; nt < 8; nt++) {
            float p00 = __expf(s[nt][0] * scale - mn0);
            float p01 = __expf(s[nt][1] * scale - mn0);
            float p10 = __expf(s[nt][2] * scale - mn1);
            float p11 = __expf(s[nt][3] * scale - mn1);
            sum0 += p00 + p01;
            sum1 += p10 + p11;
            s[nt][0] = __uint_as_float(cvt_tf32(p00));
            s[nt][1] = __uint_as_float(cvt_tf32(p01));
            s[nt][2] = __uint_as_float(cvt_tf32(p10));
            s[nt][3] = __uint_as_float(cvt_tf32(p11));
        }
#pragma unroll
        for (int off = 1; off < 4; off <<= 1) {
            sum0 += __shfl_xor_sync(0xffffffffu, sum0, off);
            sum1 += __shfl_xor_sync(0xffffffffu, sum1, off);
        }
        l0 = l0 * a0 + sum0;
        l1 = l1 * a1 + sum1;
        m0r = mn0; m1r = mn1;
#pragma unroll
        for (int nt = 0; nt < 16; nt++) {
            o[nt][0] *= a0; o[nt][1] *= a0;
            o[nt][2] *= a1; o[nt][3] *= a1;
        }

        // ---- O += P * V : V^T fragments via ldmatrix.x4 (2 nt per LDSM) ----
#pragma unroll
        for (int ks2 = 0; ks2 < 8; ks2++) {
            float e0, e1;
            uint32_t af[4];
            e0 = __shfl_sync(0xffffffffu, s[ks2][0], qsl);
            e1 = __shfl_sync(0xffffffffu, s[ks2][1], qsl);
            af[0] = __float_as_uint((tg & 1) ? e1 : e0);
            e0 = __shfl_sync(0xffffffffu, s[ks2][2], qsl);
            e1 = __shfl_sync(0xffffffffu, s[ks2][3], qsl);
            af[1] = __float_as_uint((tg & 1) ? e1 : e0);
            e0 = __shfl_sync(0xffffffffu, s[ks2][0], qsl2);
            e1 = __shfl_sync(0xffffffffu, s[ks2][1], qsl2);
            af[2] = __float_as_uint((tg & 1) ? e1 : e0);
            e0 = __shfl_sync(0xffffffffu, s[ks2][2], qsl2);
            e1 = __shfl_sync(0xffffffffu, s[ks2][3], qsl2);
            af[3] = __float_as_uint((tg & 1) ? e1 : e0);
#pragma unroll
            for (int p = 0; p < 8; p++) {
                uint32_t b0, b1, b2, b3;
                uint32_t addr = vOff +
                    (uint32_t)(((p * 16 + lrow8) * PADVT + ks2 * 8 + lcolh) * 4);
                ldsm4(b0, b1, b2, b3, addr);
                uint32_t bf0[2] = {b0, b1}, bf1[2] = {b2, b3};
                mma_tf32(o[2 * p],     af, bf0, o[2 * p]);
                mma_tf32(o[2 * p + 1], af, bf1, o[2 * p + 1]);
            }
        }
        __syncthreads();

        if (blk + 1 < nb) load_vt(blk + 1);
        CP_COMMIT();
        if (blk + 2 < nb) load_k(blk + 2, (blk & 1) ? OFF_K1 : OFF_K0);
        CP_COMMIT();
    }

    // ---- epilogue (tf32-rounded for out-projection path) ----
    const float inv0 = 1.f / l0;
    const float inv1 = 1.f / l1;
    float* ob = O + (size_t)(b * SEQ + q0 + wid * 16) * HID + h * HD;
#pragma unroll
    for (int nt = 0; nt < 16; nt++) {
        int c = nt * 8 + 2 * tg;
        float v0 = __uint_as_float(cvt_tf32(o[nt][0] * inv0));
        float v1 = __uint_as_float(cvt_tf32(o[nt][1] * inv0));
        float v2 = __uint_as_float(cvt_tf32(o[nt][2] * inv1));
        float v3 = __uint_as_float(cvt_tf32(o[nt][3] * inv1));
        *(float2*)&ob[(size_t)grp * HID + c] = make_float2(v0, v1);
        *(float2*)&ob[(size_t)(grp + 8) * HID + c] = make_float2(v2, v3);
    }
}

// ===========================================================================
extern "C" void kernel_launch(void* const* d_in, const int* in_sizes, int n_in,
                              void* d_out, int out_size)
{
    const float* x  = (const float*)d_in[0];
    const float* wq = (const float*)d_in[1];
    const float* wk = (const float*)d_in[2];
    const float* wv = (const float*)d_in[3];
    const float* wo = (const float*)d_in[4];
    float* out = (float*)d_out;

    float *q, *k, *vt, *o, *xr, *wqr, *wor;
    cudaGetSymbolAddress((void**)&q, g_q);
    cudaGetSymbolAddress((void**)&k, g_k);
    cudaGetSymbolAddress((void**)&vt, g_vt);
    cudaGetSymbolAddress((void**)&o, g_o);
    cudaGetSymbolAddress((void**)&xr, g_x);
    cudaGetSymbolAddress((void**)&wqr, g_wq);
    cudaGetSymbolAddress((void**)&wor, g_wo);

    cudaFuncSetAttribute(flash_mqa_tc,
                         cudaFuncAttributeMaxDynamicSharedMemorySize, FLASH_SMEM);
    cudaFuncSetAttribute(gemm_wide,
                         cudaFuncAttributeMaxDynamicSharedMemorySize, WSMEM);

    dim3 blk(256);

    // Round x, w_q, w_out to tf32
    round3_tf32<<<2048, 256>>>(x, xr, MROWS * HID / 4,
                               wq, wqr, HID * HID / 4,
                               wo, wor, HID * HID / 4);

    // Q projection (wide tensor GEMM, tf32-rounded output)
    gemm_wide<<<dim3(HID / 256, MROWS / 128), blk, WSMEM>>>(
        xr, wqr, q, MROWS, HID, HID, 1);

    // K (normal) and V (transposed) projections fused
    gemm_kv<<<dim3(HD / 128, MROWS / 128, 2), blk>>>(
        x, wk, k, MROWS, HD, HID, wv, vt);

    // Tensor-core flash attention (ldmatrix fragments)
    flash_mqa_tc<<<dim3(BATCH * NH, SEQ / BQ), blk, FLASH_SMEM>>>(q, k, vt, o);

    // Output projection (wide tensor GEMM, full fp32 output)
    gemm_wide<<<dim3(HID / 256, MROWS / 128), blk, WSMEM>>>(
        o, wor, out, MROWS, HID, HID, 0);
}